// round 1
// baseline (speedup 1.0000x reference)
#include <cuda_runtime.h>
#include <math.h>

#define B_ 4
#define T_ 2048
#define C_ 1024
#define H_ 16
#define D_ 64
#define M_ (B_*T_)   // 8192

// Scratch (allocation-free): qkv buffer [8192, 3072], attention output [8192, 1024]
__device__ float g_qkv[25165824];   // 8192*3072
__device__ float g_att[8388608];    // 8192*1024

// ---------------------------------------------------------------------------
// Tiled FP32 SGEMM with bias: C[M,N] = A[M,K] @ B[K,N] + bias[N]
// BM=BN=128, BK=8, 256 threads, 8x8 per-thread tile.
// ---------------------------------------------------------------------------
__global__ void __launch_bounds__(256) sgemm_bias_kernel(
    const float* __restrict__ A, const float* __restrict__ Bm,
    const float* __restrict__ bias, float* __restrict__ Cm,
    int M, int N, int K)
{
    __shared__ float As[8][128];   // transposed A tile
    __shared__ float Bs[8][128];

    const int tid = threadIdx.x;
    const int mBase = blockIdx.y * 128;
    const int nBase = blockIdx.x * 128;
    const int aRow = tid >> 1;            // 0..127
    const int aCol = (tid & 1) << 2;      // 0 or 4
    const int bRow = tid >> 5;            // 0..7
    const int bCol = (tid & 31) << 2;     // 0..124
    const int ty = tid >> 4;              // 0..15
    const int tx = tid & 15;              // 0..15

    const float* Ap = A + (size_t)(mBase + aRow) * K + aCol;
    const float* Bp = Bm + (size_t)bRow * N + (nBase + bCol);

    float acc[8][8] = {};

    for (int kb = 0; kb < K; kb += 8) {
        float4 a4 = *(const float4*)(Ap + kb);
        float4 b4 = *(const float4*)(Bp + (size_t)kb * N);
        __syncthreads();
        As[aCol+0][aRow] = a4.x;
        As[aCol+1][aRow] = a4.y;
        As[aCol+2][aRow] = a4.z;
        As[aCol+3][aRow] = a4.w;
        *(float4*)&Bs[bRow][bCol] = b4;
        __syncthreads();
        #pragma unroll
        for (int k = 0; k < 8; k++) {
            float ar[8], br[8];
            *(float4*)&ar[0] = *(const float4*)&As[k][ty*8];
            *(float4*)&ar[4] = *(const float4*)&As[k][ty*8+4];
            *(float4*)&br[0] = *(const float4*)&Bs[k][tx*8];
            *(float4*)&br[4] = *(const float4*)&Bs[k][tx*8+4];
            #pragma unroll
            for (int i = 0; i < 8; i++)
                #pragma unroll
                for (int j = 0; j < 8; j++)
                    acc[i][j] += ar[i] * br[j];
        }
    }

    const int row0 = mBase + ty*8;
    const int col0 = nBase + tx*8;
    float bb[8];
    #pragma unroll
    for (int j = 0; j < 8; j++) bb[j] = bias[col0 + j];
    #pragma unroll
    for (int i = 0; i < 8; i++) {
        float4 c0, c1;
        c0.x = acc[i][0]+bb[0]; c0.y = acc[i][1]+bb[1];
        c0.z = acc[i][2]+bb[2]; c0.w = acc[i][3]+bb[3];
        c1.x = acc[i][4]+bb[4]; c1.y = acc[i][5]+bb[5];
        c1.z = acc[i][6]+bb[6]; c1.w = acc[i][7]+bb[7];
        size_t off = (size_t)(row0+i)*N + col0;
        *(float4*)(Cm + off)     = c0;
        *(float4*)(Cm + off + 4) = c1;
    }
}

// ---------------------------------------------------------------------------
// Flash-attention (fp32, causal). One block = 64 q rows of one (b,h).
// 256 threads, 16x16 grid, 4x4 per-thread S/O tiles, online softmax.
// K tile stored transposed [d][k] with XOR chunk swizzle for conflict-free
// LDS.128 in the QK^T inner loop. Causal: inner loop only kt <= qt.
// ---------------------------------------------------------------------------
#define SMEM_ATTN ((64*65 + 64*64 + 64*65 + 64*64)*4)

__global__ void __launch_bounds__(256) attn_kernel(const float* __restrict__ qkv,
                                                   float* __restrict__ att)
{
    extern __shared__ float sm[];
    float* Qs = sm;                // [64][65]
    float* Ks = Qs + 64*65;        // [64][64] KsT[d][k], swizzled
    float* Ps = Ks + 64*64;        // [64][65]
    float* Vs = Ps + 64*65;        // [64][64]

    const int tid = threadIdx.x;
    const int ty = tid >> 4, tx = tid & 15;
    const int ty4 = ty << 2, tx4 = tx << 2;
    const int bh = blockIdx.y;
    const int b = bh >> 4, h = bh & 15;
    // launch biggest blocks (largest qt) first to reduce tail imbalance
    const int qt = (int)gridDim.x - 1 - (int)blockIdx.x;
    const int q0 = qt << 6;
    const size_t ld = 3 * C_;
    const float* qbase = qkv + (size_t)b * T_ * ld + h * D_;
    const float* kbase = qbase + C_;
    const float* vbase = qbase + 2 * C_;

    // Load Q tile once: Qs[r][d], pad 65
    #pragma unroll
    for (int it = 0; it < 4; it++) {
        int e = it*256 + tid;
        int r = e >> 4;
        int d4 = (e & 15) << 2;
        float4 v = *(const float4*)(qbase + (size_t)(q0 + r)*ld + d4);
        float* dst = Qs + r*65 + d4;
        dst[0]=v.x; dst[1]=v.y; dst[2]=v.z; dst[3]=v.w;
    }

    float m[4], l[4], o[4][4];
    #pragma unroll
    for (int i = 0; i < 4; i++) {
        m[i] = -1e30f; l[i] = 0.f;
        #pragma unroll
        for (int j = 0; j < 4; j++) o[i][j] = 0.f;
    }

    for (int kt = 0; kt <= qt; kt++) {
        const int k0 = kt << 6;
        __syncthreads();   // protect Ks/Vs/Ps from previous iteration readers
        // Load K (transposed+swizzled) and V tiles
        #pragma unroll
        for (int it = 0; it < 4; it++) {
            int e = it*256 + tid;
            int r = e >> 4;
            int mm = e & 15;
            int d4 = mm << 2;
            float4 kv = *(const float4*)(kbase + (size_t)(k0 + r)*ld + d4);
            int pos = ((((r >> 2) ^ mm) << 2) | (r & 3));
            Ks[(d4+0)*64 + pos] = kv.x;
            Ks[(d4+1)*64 + pos] = kv.y;
            Ks[(d4+2)*64 + pos] = kv.z;
            Ks[(d4+3)*64 + pos] = kv.w;
            float4 vv = *(const float4*)(vbase + (size_t)(k0 + r)*ld + d4);
            *(float4*)(Vs + r*64 + d4) = vv;
        }
        __syncthreads();

        // S = Q @ K^T
        float s[4][4];
        #pragma unroll
        for (int i = 0; i < 4; i++)
            #pragma unroll
            for (int j = 0; j < 4; j++) s[i][j] = 0.f;

        #pragma unroll 16
        for (int d = 0; d < 64; d++) {
            float q0r = Qs[(ty4+0)*65 + d];
            float q1r = Qs[(ty4+1)*65 + d];
            float q2r = Qs[(ty4+2)*65 + d];
            float q3r = Qs[(ty4+3)*65 + d];
            const float4 kv = *(const float4*)(Ks + d*64 + ((tx ^ ((d >> 2) & 15)) << 2));
            s[0][0] += q0r*kv.x; s[0][1] += q0r*kv.y; s[0][2] += q0r*kv.z; s[0][3] += q0r*kv.w;
            s[1][0] += q1r*kv.x; s[1][1] += q1r*kv.y; s[1][2] += q1r*kv.z; s[1][3] += q1r*kv.w;
            s[2][0] += q2r*kv.x; s[2][1] += q2r*kv.y; s[2][2] += q2r*kv.z; s[2][3] += q2r*kv.w;
            s[3][0] += q3r*kv.x; s[3][1] += q3r*kv.y; s[3][2] += q3r*kv.z; s[3][3] += q3r*kv.w;
        }

        // Online softmax (rows grouped across the 16 tx lanes, same warp half)
        const bool diag = (kt == qt);
        #pragma unroll
        for (int i = 0; i < 4; i++) {
            float rm = -1e30f;
            #pragma unroll
            for (int j = 0; j < 4; j++) {
                float sv = s[i][j] * 0.125f;   // 1/sqrt(64)
                if (diag && (tx4 + j) > (ty4 + i)) sv = -1e30f;
                s[i][j] = sv;
                rm = fmaxf(rm, sv);
            }
            rm = fmaxf(rm, __shfl_xor_sync(0xffffffffu, rm, 8));
            rm = fmaxf(rm, __shfl_xor_sync(0xffffffffu, rm, 4));
            rm = fmaxf(rm, __shfl_xor_sync(0xffffffffu, rm, 2));
            rm = fmaxf(rm, __shfl_xor_sync(0xffffffffu, rm, 1));
            float mn = fmaxf(m[i], rm);
            float corr = __expf(m[i] - mn);
            float ps = 0.f;
            #pragma unroll
            for (int j = 0; j < 4; j++) {
                float p = __expf(s[i][j] - mn);
                s[i][j] = p;
                ps += p;
            }
            ps += __shfl_xor_sync(0xffffffffu, ps, 8);
            ps += __shfl_xor_sync(0xffffffffu, ps, 4);
            ps += __shfl_xor_sync(0xffffffffu, ps, 2);
            ps += __shfl_xor_sync(0xffffffffu, ps, 1);
            l[i] = l[i]*corr + ps;
            m[i] = mn;
            #pragma unroll
            for (int j = 0; j < 4; j++) o[i][j] *= corr;
            float* pr = Ps + (ty4+i)*65 + tx4;
            pr[0] = s[i][0]; pr[1] = s[i][1]; pr[2] = s[i][2]; pr[3] = s[i][3];
        }
        __syncthreads();

        // O += P @ V
        #pragma unroll 16
        for (int k = 0; k < 64; k++) {
            float p0 = Ps[(ty4+0)*65 + k];
            float p1 = Ps[(ty4+1)*65 + k];
            float p2 = Ps[(ty4+2)*65 + k];
            float p3 = Ps[(ty4+3)*65 + k];
            const float4 vv = *(const float4*)(Vs + k*64 + tx4);
            o[0][0] += p0*vv.x; o[0][1] += p0*vv.y; o[0][2] += p0*vv.z; o[0][3] += p0*vv.w;
            o[1][0] += p1*vv.x; o[1][1] += p1*vv.y; o[1][2] += p1*vv.z; o[1][3] += p1*vv.w;
            o[2][0] += p2*vv.x; o[2][1] += p2*vv.y; o[2][2] += p2*vv.z; o[2][3] += p2*vv.w;
            o[3][0] += p3*vv.x; o[3][1] += p3*vv.y; o[3][2] += p3*vv.z; o[3][3] += p3*vv.w;
        }
    }

    // Epilogue: normalize and write [b*T+t][h*64+d]
    float* obase = att + (size_t)(b*T_ + q0) * C_ + h * D_;
    #pragma unroll
    for (int i = 0; i < 4; i++) {
        float inv = 1.f / l[i];
        float4 r;
        r.x = o[i][0]*inv; r.y = o[i][1]*inv; r.z = o[i][2]*inv; r.w = o[i][3]*inv;
        *(float4*)(obase + (size_t)(ty4+i)*C_ + tx4) = r;
    }
}

// ---------------------------------------------------------------------------
extern "C" void kernel_launch(void* const* d_in, const int* in_sizes, int n_in,
                              void* d_out, int out_size)
{
    const float* x      = (const float*)d_in[0];
    const float* w_qkv  = (const float*)d_in[1];
    const float* b_qkv  = (const float*)d_in[2];
    const float* w_proj = (const float*)d_in[3];
    const float* b_proj = (const float*)d_in[4];
    float* out = (float*)d_out;

    float *qkv_ptr = nullptr, *att_ptr = nullptr;
    cudaGetSymbolAddress((void**)&qkv_ptr, g_qkv);
    cudaGetSymbolAddress((void**)&att_ptr, g_att);

    cudaFuncSetAttribute(attn_kernel,
                         cudaFuncAttributeMaxDynamicSharedMemorySize, SMEM_ATTN);

    dim3 blk(256);

    // 1) qkv = x @ w_qkv + b_qkv   [8192, 3072]
    dim3 g1(3*C_/128, M_/128);
    sgemm_bias_kernel<<<g1, blk>>>(x, w_qkv, b_qkv, qkv_ptr, M_, 3*C_, C_);

    // 2) causal flash attention -> g_att [8192, 1024]
    dim3 g2(T_/64, B_*H_);
    attn_kernel<<<g2, blk, SMEM_ATTN>>>(qkv_ptr, att_ptr);

    // 3) out = att @ w_proj + b_proj   [8192, 1024]
    dim3 g3(C_/128, M_/128);
    sgemm_bias_kernel<<<g3, blk>>>(att_ptr, w_proj, b_proj, out, M_, C_, C_);
}

// round 2
// speedup vs baseline: 1.0586x; 1.0586x over previous
#include <cuda_runtime.h>
#include <math.h>

#define B_ 4
#define T_ 2048
#define C_ 1024
#define H_ 16
#define D_ 64
#define M_ (B_*T_)   // 8192

// Scratch (allocation-free): qkv buffer [8192, 3072], attention output [8192, 1024]
__device__ float g_qkv[25165824];   // 8192*3072
__device__ float g_att[8388608];    // 8192*1024

// ---------------------------------------------------------------------------
// Tiled FP32 SGEMM with bias: C[M,N] = A[M,K] @ B[K,N] + bias[N]
// BM=BN=128, BK=8, 256 threads, 8x8 per-thread tile.
// ---------------------------------------------------------------------------
__global__ void __launch_bounds__(256) sgemm_bias_kernel(
    const float* __restrict__ A, const float* __restrict__ Bm,
    const float* __restrict__ bias, float* __restrict__ Cm,
    int M, int N, int K)
{
    __shared__ float As[8][128];   // transposed A tile
    __shared__ float Bs[8][128];

    const int tid = threadIdx.x;
    const int mBase = blockIdx.y * 128;
    const int nBase = blockIdx.x * 128;
    const int aRow = tid >> 1;            // 0..127
    const int aCol = (tid & 1) << 2;      // 0 or 4
    const int bRow = tid >> 5;            // 0..7
    const int bCol = (tid & 31) << 2;     // 0..124
    const int ty = tid >> 4;              // 0..15
    const int tx = tid & 15;              // 0..15

    const float* Ap = A + (size_t)(mBase + aRow) * K + aCol;
    const float* Bp = Bm + (size_t)bRow * N + (nBase + bCol);

    float acc[8][8] = {};

    for (int kb = 0; kb < K; kb += 8) {
        float4 a4 = *(const float4*)(Ap + kb);
        float4 b4 = *(const float4*)(Bp + (size_t)kb * N);
        __syncthreads();
        As[aCol+0][aRow] = a4.x;
        As[aCol+1][aRow] = a4.y;
        As[aCol+2][aRow] = a4.z;
        As[aCol+3][aRow] = a4.w;
        *(float4*)&Bs[bRow][bCol] = b4;
        __syncthreads();
        #pragma unroll
        for (int k = 0; k < 8; k++) {
            float ar[8], br[8];
            *(float4*)&ar[0] = *(const float4*)&As[k][ty*8];
            *(float4*)&ar[4] = *(const float4*)&As[k][ty*8+4];
            *(float4*)&br[0] = *(const float4*)&Bs[k][tx*8];
            *(float4*)&br[4] = *(const float4*)&Bs[k][tx*8+4];
            #pragma unroll
            for (int i = 0; i < 8; i++)
                #pragma unroll
                for (int j = 0; j < 8; j++)
                    acc[i][j] += ar[i] * br[j];
        }
    }

    const int row0 = mBase + ty*8;
    const int col0 = nBase + tx*8;
    float bb[8];
    #pragma unroll
    for (int j = 0; j < 8; j++) bb[j] = bias[col0 + j];
    #pragma unroll
    for (int i = 0; i < 8; i++) {
        float4 c0, c1;
        c0.x = acc[i][0]+bb[0]; c0.y = acc[i][1]+bb[1];
        c0.z = acc[i][2]+bb[2]; c0.w = acc[i][3]+bb[3];
        c1.x = acc[i][4]+bb[4]; c1.y = acc[i][5]+bb[5];
        c1.z = acc[i][6]+bb[6]; c1.w = acc[i][7]+bb[7];
        size_t off = (size_t)(row0+i)*N + col0;
        *(float4*)(Cm + off)     = c0;
        *(float4*)(Cm + off + 4) = c1;
    }
}

// ---------------------------------------------------------------------------
// Flash-attention (fp32, causal). One block = 64 q rows of one (b,h).
// 256 threads, 16x16 grid, 4x4 per-thread S/O tiles, online softmax.
// K tile stored transposed [d][k] with XOR chunk swizzle for conflict-free
// LDS.128 in the QK^T inner loop. Causal: inner loop only kt <= qt.
// ---------------------------------------------------------------------------
#define SMEM_ATTN ((64*65 + 64*64 + 64*65 + 64*64)*4)

__global__ void __launch_bounds__(256) attn_kernel(const float* __restrict__ qkv,
                                                   float* __restrict__ att)
{
    extern __shared__ float sm[];
    float* Qs = sm;                // [64][65]
    float* Ks = Qs + 64*65;        // [64][64] KsT[d][k], swizzled
    float* Ps = Ks + 64*64;        // [64][65]
    float* Vs = Ps + 64*65;        // [64][64]

    const int tid = threadIdx.x;
    const int ty = tid >> 4, tx = tid & 15;
    const int ty4 = ty << 2, tx4 = tx << 2;
    const int bh = blockIdx.y;
    const int b = bh >> 4, h = bh & 15;
    // launch biggest blocks (largest qt) first to reduce tail imbalance
    const int qt = (int)gridDim.x - 1 - (int)blockIdx.x;
    const int q0 = qt << 6;
    const size_t ld = 3 * C_;
    const float* qbase = qkv + (size_t)b * T_ * ld + h * D_;
    const float* kbase = qbase + C_;
    const float* vbase = qbase + 2 * C_;

    // Load Q tile once: Qs[r][d], pad 65
    #pragma unroll
    for (int it = 0; it < 4; it++) {
        int e = it*256 + tid;
        int r = e >> 4;
        int d4 = (e & 15) << 2;
        float4 v = *(const float4*)(qbase + (size_t)(q0 + r)*ld + d4);
        float* dst = Qs + r*65 + d4;
        dst[0]=v.x; dst[1]=v.y; dst[2]=v.z; dst[3]=v.w;
    }

    float m[4], l[4], o[4][4];
    #pragma unroll
    for (int i = 0; i < 4; i++) {
        m[i] = -1e30f; l[i] = 0.f;
        #pragma unroll
        for (int j = 0; j < 4; j++) o[i][j] = 0.f;
    }

    for (int kt = 0; kt <= qt; kt++) {
        const int k0 = kt << 6;
        __syncthreads();   // protect Ks/Vs/Ps from previous iteration readers
        // Load K (transposed+swizzled) and V tiles
        #pragma unroll
        for (int it = 0; it < 4; it++) {
            int e = it*256 + tid;
            int r = e >> 4;
            int mm = e & 15;
            int d4 = mm << 2;
            float4 kv = *(const float4*)(kbase + (size_t)(k0 + r)*ld + d4);
            int pos = ((((r >> 2) ^ mm) << 2) | (r & 3));
            Ks[(d4+0)*64 + pos] = kv.x;
            Ks[(d4+1)*64 + pos] = kv.y;
            Ks[(d4+2)*64 + pos] = kv.z;
            Ks[(d4+3)*64 + pos] = kv.w;
            float4 vv = *(const float4*)(vbase + (size_t)(k0 + r)*ld + d4);
            *(float4*)(Vs + r*64 + d4) = vv;
        }
        __syncthreads();

        // S = Q @ K^T
        float s[4][4];
        #pragma unroll
        for (int i = 0; i < 4; i++)
            #pragma unroll
            for (int j = 0; j < 4; j++) s[i][j] = 0.f;

        #pragma unroll 16
        for (int d = 0; d < 64; d++) {
            float q0r = Qs[(ty4+0)*65 + d];
            float q1r = Qs[(ty4+1)*65 + d];
            float q2r = Qs[(ty4+2)*65 + d];
            float q3r = Qs[(ty4+3)*65 + d];
            const float4 kv = *(const float4*)(Ks + d*64 + ((tx ^ ((d >> 2) & 15)) << 2));
            s[0][0] += q0r*kv.x; s[0][1] += q0r*kv.y; s[0][2] += q0r*kv.z; s[0][3] += q0r*kv.w;
            s[1][0] += q1r*kv.x; s[1][1] += q1r*kv.y; s[1][2] += q1r*kv.z; s[1][3] += q1r*kv.w;
            s[2][0] += q2r*kv.x; s[2][1] += q2r*kv.y; s[2][2] += q2r*kv.z; s[2][3] += q2r*kv.w;
            s[3][0] += q3r*kv.x; s[3][1] += q3r*kv.y; s[3][2] += q3r*kv.z; s[3][3] += q3r*kv.w;
        }

        // Online softmax (rows grouped across the 16 tx lanes, same warp half)
        const bool diag = (kt == qt);
        #pragma unroll
        for (int i = 0; i < 4; i++) {
            float rm = -1e30f;
            #pragma unroll
            for (int j = 0; j < 4; j++) {
                float sv = s[i][j] * 0.125f;   // 1/sqrt(64)
                if (diag && (tx4 + j) > (ty4 + i)) sv = -1e30f;
                s[i][j] = sv;
                rm = fmaxf(rm, sv);
            }
            rm = fmaxf(rm, __shfl_xor_sync(0xffffffffu, rm, 8));
            rm = fmaxf(rm, __shfl_xor_sync(0xffffffffu, rm, 4));
            rm = fmaxf(rm, __shfl_xor_sync(0xffffffffu, rm, 2));
            rm = fmaxf(rm, __shfl_xor_sync(0xffffffffu, rm, 1));
            float mn = fmaxf(m[i], rm);
            float corr = __expf(m[i] - mn);
            float ps = 0.f;
            #pragma unroll
            for (int j = 0; j < 4; j++) {
                float p = __expf(s[i][j] - mn);
                s[i][j] = p;
                ps += p;
            }
            ps += __shfl_xor_sync(0xffffffffu, ps, 8);
            ps += __shfl_xor_sync(0xffffffffu, ps, 4);
            ps += __shfl_xor_sync(0xffffffffu, ps, 2);
            ps += __shfl_xor_sync(0xffffffffu, ps, 1);
            l[i] = l[i]*corr + ps;
            m[i] = mn;
            #pragma unroll
            for (int j = 0; j < 4; j++) o[i][j] *= corr;
            float* pr = Ps + (ty4+i)*65 + tx4;
            pr[0] = s[i][0]; pr[1] = s[i][1]; pr[2] = s[i][2]; pr[3] = s[i][3];
        }
        __syncthreads();

        // O += P @ V
        #pragma unroll 16
        for (int k = 0; k < 64; k++) {
            float p0 = Ps[(ty4+0)*65 + k];
            float p1 = Ps[(ty4+1)*65 + k];
            float p2 = Ps[(ty4+2)*65 + k];
            float p3 = Ps[(ty4+3)*65 + k];
            const float4 vv = *(const float4*)(Vs + k*64 + tx4);
            o[0][0] += p0*vv.x; o[0][1] += p0*vv.y; o[0][2] += p0*vv.z; o[0][3] += p0*vv.w;
            o[1][0] += p1*vv.x; o[1][1] += p1*vv.y; o[1][2] += p1*vv.z; o[1][3] += p1*vv.w;
            o[2][0] += p2*vv.x; o[2][1] += p2*vv.y; o[2][2] += p2*vv.z; o[2][3] += p2*vv.w;
            o[3][0] += p3*vv.x; o[3][1] += p3*vv.y; o[3][2] += p3*vv.z; o[3][3] += p3*vv.w;
        }
    }

    // Epilogue: normalize and write [b*T+t][h*64+d]
    float* obase = att + (size_t)(b*T_ + q0) * C_ + h * D_;
    #pragma unroll
    for (int i = 0; i < 4; i++) {
        float inv = 1.f / l[i];
        float4 r;
        r.x = o[i][0]*inv; r.y = o[i][1]*inv; r.z = o[i][2]*inv; r.w = o[i][3]*inv;
        *(float4*)(obase + (size_t)(ty4+i)*C_ + tx4) = r;
    }
}

// ---------------------------------------------------------------------------
extern "C" void kernel_launch(void* const* d_in, const int* in_sizes, int n_in,
                              void* d_out, int out_size)
{
    const float* x      = (const float*)d_in[0];
    const float* w_qkv  = (const float*)d_in[1];
    const float* b_qkv  = (const float*)d_in[2];
    const float* w_proj = (const float*)d_in[3];
    const float* b_proj = (const float*)d_in[4];
    float* out = (float*)d_out;

    float *qkv_ptr = nullptr, *att_ptr = nullptr;
    cudaGetSymbolAddress((void**)&qkv_ptr, g_qkv);
    cudaGetSymbolAddress((void**)&att_ptr, g_att);

    cudaFuncSetAttribute(attn_kernel,
                         cudaFuncAttributeMaxDynamicSharedMemorySize, SMEM_ATTN);

    dim3 blk(256);

    // 1) qkv = x @ w_qkv + b_qkv   [8192, 3072]
    dim3 g1(3*C_/128, M_/128);
    sgemm_bias_kernel<<<g1, blk>>>(x, w_qkv, b_qkv, qkv_ptr, M_, 3*C_, C_);

    // 2) causal flash attention -> g_att [8192, 1024]
    dim3 g2(T_/64, B_*H_);
    attn_kernel<<<g2, blk, SMEM_ATTN>>>(qkv_ptr, att_ptr);

    // 3) out = att @ w_proj + b_proj   [8192, 1024]
    dim3 g3(C_/128, M_/128);
    sgemm_bias_kernel<<<g3, blk>>>(att_ptr, w_proj, b_proj, out, M_, C_, C_);
}

// round 5
// speedup vs baseline: 1.7110x; 1.6163x over previous
#include <cuda_runtime.h>
#include <cuda_bf16.h>
#include <stdint.h>
#include <math.h>

#define B_ 4
#define T_ 2048
#define C_ 1024
#define H_ 16
#define D_ 64
#define M_ (B_*T_)   // 8192

// ---------------------------------------------------------------------------
// Scratch (allocation-free __device__ globals)
// ---------------------------------------------------------------------------
__device__ float          g_qkv[25165824];     // [8192,3072] fp32 attention input
__device__ unsigned short g_xh[8388608];       // x hi bf16 [8192][1024]
__device__ unsigned short g_xl[8388608];       // x lo
__device__ unsigned short g_wqkvh[3145728];    // w_qkv^T hi [3072][1024]
__device__ unsigned short g_wqkvl[3145728];
__device__ unsigned short g_wprojh[1048576];   // w_proj^T hi [1024][1024]
__device__ unsigned short g_wprojl[1048576];
__device__ unsigned short g_atth[8388608];     // attention out hi [8192][1024]
__device__ unsigned short g_attl[8388608];

// ---------------------------------------------------------------------------
// Helpers (sm_103 baseline features only: ldmatrix, mma.sync, cp.async)
// ---------------------------------------------------------------------------
__device__ __forceinline__ uint32_t smem_u32(const void* p) {
    uint32_t a;
    asm("{ .reg .u64 t; cvta.to.shared.u64 t, %1; cvt.u32.u64 %0, t; }"
        : "=r"(a) : "l"(p));
    return a;
}

__device__ __forceinline__ void ldsm_x4(uint32_t& r0, uint32_t& r1,
                                        uint32_t& r2, uint32_t& r3, uint32_t a) {
    asm volatile("ldmatrix.sync.aligned.m8n8.x4.shared.b16 {%0,%1,%2,%3}, [%4];"
                 : "=r"(r0), "=r"(r1), "=r"(r2), "=r"(r3) : "r"(a));
}

// NON-trans: B stored [N][K] (K contiguous) is already the col-major operand.
__device__ __forceinline__ void ldsm_x2(uint32_t& r0, uint32_t& r1, uint32_t a) {
    asm volatile("ldmatrix.sync.aligned.m8n8.x2.shared.b16 {%0,%1}, [%2];"
                 : "=r"(r0), "=r"(r1) : "r"(a));
}

__device__ __forceinline__ void mma16816(float* c, const uint32_t* A, const uint32_t* Bv) {
    asm volatile(
        "mma.sync.aligned.m16n8k16.row.col.f32.bf16.bf16.f32 "
        "{%0,%1,%2,%3}, {%4,%5,%6,%7}, {%8,%9}, {%0,%1,%2,%3};"
        : "+f"(c[0]), "+f"(c[1]), "+f"(c[2]), "+f"(c[3])
        : "r"(A[0]), "r"(A[1]), "r"(A[2]), "r"(A[3]), "r"(Bv[0]), "r"(Bv[1]));
}

__device__ __forceinline__ void cp16(uint32_t dst, const void* src) {
    asm volatile("cp.async.cg.shared.global [%0], [%1], 16;" :: "r"(dst), "l"(src));
}
#define CP_COMMIT() asm volatile("cp.async.commit_group;" ::: "memory")
#define CP_WAIT0()  asm volatile("cp.async.wait_group 0;" ::: "memory")

__device__ __forceinline__ void split2(float x, unsigned short& hh, unsigned short& ll) {
    __nv_bfloat16 hb = __float2bfloat16(x);
    hh = reinterpret_cast<unsigned short&>(hb);
    float r = x - __bfloat162float(hb);
    __nv_bfloat16 lb = __float2bfloat16(r);
    ll = reinterpret_cast<unsigned short&>(lb);
}

// ---------------------------------------------------------------------------
// Prep: fp32 [n] -> hi/lo bf16 (4 elems per thread)
// ---------------------------------------------------------------------------
__global__ void __launch_bounds__(256) pack_split_kernel(
    const float* __restrict__ src, unsigned short* __restrict__ hi,
    unsigned short* __restrict__ lo)
{
    int i = blockIdx.x * 256 + threadIdx.x;
    float4 v = ((const float4*)src)[i];
    unsigned short h[4], l[4];
    split2(v.x, h[0], l[0]); split2(v.y, h[1], l[1]);
    split2(v.z, h[2], l[2]); split2(v.w, h[3], l[3]);
    ((uint2*)hi)[i] = make_uint2((uint32_t)h[0] | ((uint32_t)h[1] << 16),
                                 (uint32_t)h[2] | ((uint32_t)h[3] << 16));
    ((uint2*)lo)[i] = make_uint2((uint32_t)l[0] | ((uint32_t)l[1] << 16),
                                 (uint32_t)l[2] | ((uint32_t)l[3] << 16));
}

// ---------------------------------------------------------------------------
// Prep: w [K,N] fp32 -> wT hi/lo bf16 [N,K]
// ---------------------------------------------------------------------------
__global__ void __launch_bounds__(256) transpose_pack_kernel(
    const float* __restrict__ w, unsigned short* __restrict__ th,
    unsigned short* __restrict__ tl, int K, int N)
{
    __shared__ float tile[32][33];
    const int k0 = blockIdx.y * 32, n0 = blockIdx.x * 32;
    const int tx = threadIdx.x, ty = threadIdx.y;   // 32 x 8
    #pragma unroll
    for (int i = 0; i < 32; i += 8)
        tile[ty + i][tx] = w[(size_t)(k0 + ty + i) * N + n0 + tx];
    __syncthreads();
    #pragma unroll
    for (int i = 0; i < 32; i += 8) {
        int n = n0 + ty + i;
        int k = k0 + tx;
        float v = tile[tx][ty + i];
        unsigned short hh, ll;
        split2(v, hh, ll);
        th[(size_t)n * K + k] = hh;
        tl[(size_t)n * K + k] = ll;
    }
}

// ---------------------------------------------------------------------------
// Split-bf16 mma.sync GEMM: out[M,N] = A[M,K] @ B^T[N,K] + bias
// BM=BN=128, BK=32, 256 threads (8 warps, 2x4), warp tile 64x32.
// cp.async double-buffered smem; swizzled 16B chunks for ldmatrix.
// Smem stage layout: Ah[128][32] Al Bh Bl, 8KB each, 32KB/stage, 2 stages.
// ---------------------------------------------------------------------------
#define GEMM_SMEM 65536

__global__ void __launch_bounds__(256) gemm_mma_kernel(
    const unsigned short* __restrict__ ah, const unsigned short* __restrict__ al,
    const unsigned short* __restrict__ bh, const unsigned short* __restrict__ bl,
    const float* __restrict__ bias, float* __restrict__ out,
    int M, int N, int K)
{
    extern __shared__ char smc[];
    const uint32_t sbase = smem_u32(smc);
    const int tid  = threadIdx.x;
    const int wid  = tid >> 5, lane = tid & 31;
    const int wm   = wid >> 2, wn = wid & 3;          // 2 x 4 warp grid
    const int mBase = blockIdx.y * 128;
    const int nBase = blockIdx.x * 128;
    const int nk = K >> 5;

    // cp.async per-thread slots: per part, 2 chunks (idx, idx+256)
    const int r0c = tid >> 2;            // rows 0..63
    const int c0c = tid & 3;             // chunk 0..3
    // swizzled chunk offset within a row: (c ^ ((r>>1)&3))*16
    auto sw = [](int r, int c) { return r * 64 + ((c ^ ((r >> 1) & 3)) << 4); };

    auto issue = [&](int ks, int stage) {
        const int kb = ks << 5;
        const unsigned short* gs[4] = { ah, al, bh, bl };
        #pragma unroll
        for (int part = 0; part < 4; part++) {
            const unsigned short* g = gs[part] +
                (size_t)((part < 2) ? mBase : nBase) * K + kb;
            uint32_t pb = sbase + stage * 32768 + part * 8192;
            cp16(pb + sw(r0c,      c0c), g + (size_t)r0c        * K + c0c * 8);
            cp16(pb + sw(r0c + 64, c0c), g + (size_t)(r0c + 64) * K + c0c * 8);
        }
        CP_COMMIT();
    };

    float acc[4][4][4];
    #pragma unroll
    for (int i = 0; i < 4; i++)
        #pragma unroll
        for (int j = 0; j < 4; j++)
            #pragma unroll
            for (int r = 0; r < 4; r++) acc[i][j][r] = 0.f;

    // ldmatrix lane address components
    const int la_row = lane & 15;          // A: rows within m16
    const int la_kh  = lane >> 4;          // A: k half (0/1)
    const int lb_row = lane & 7;           // B: rows within n8
    const int lb_kh  = (lane >> 3) & 1;    // B: k half (0/1)

    issue(0, 0);

    for (int ks = 0; ks < nk; ks++) {
        const int cur = ks & 1;
        CP_WAIT0();
        __syncthreads();
        if (ks + 1 < nk) issue(ks + 1, cur ^ 1);

        const uint32_t sAh = sbase + cur * 32768;
        const uint32_t sAl = sAh + 8192;
        const uint32_t sBh = sAh + 16384;
        const uint32_t sBl = sAh + 24576;

        #pragma unroll
        for (int kk = 0; kk < 2; kk++) {      // two k16 halves of BK=32
            uint32_t Af[4][4], Bf[4][2];
            const int ch_a = kk * 2 + la_kh;
            const int ch_b = kk * 2 + lb_kh;

            // --- Ah x Bh ---
            #pragma unroll
            for (int i = 0; i < 4; i++) {
                int row = wm * 64 + i * 16 + la_row;
                ldsm_x4(Af[i][0], Af[i][1], Af[i][2], Af[i][3], sAh + sw(row, ch_a));
            }
            #pragma unroll
            for (int j = 0; j < 4; j++) {
                int row = wn * 32 + j * 8 + lb_row;
                ldsm_x2(Bf[j][0], Bf[j][1], sBh + sw(row, ch_b));
            }
            #pragma unroll
            for (int i = 0; i < 4; i++)
                #pragma unroll
                for (int j = 0; j < 4; j++) mma16816(acc[i][j], Af[i], Bf[j]);

            // --- Ah x Bl ---
            #pragma unroll
            for (int j = 0; j < 4; j++) {
                int row = wn * 32 + j * 8 + lb_row;
                ldsm_x2(Bf[j][0], Bf[j][1], sBl + sw(row, ch_b));
            }
            #pragma unroll
            for (int i = 0; i < 4; i++)
                #pragma unroll
                for (int j = 0; j < 4; j++) mma16816(acc[i][j], Af[i], Bf[j]);

            // --- Al x Bh ---
            #pragma unroll
            for (int i = 0; i < 4; i++) {
                int row = wm * 64 + i * 16 + la_row;
                ldsm_x4(Af[i][0], Af[i][1], Af[i][2], Af[i][3], sAl + sw(row, ch_a));
            }
            #pragma unroll
            for (int j = 0; j < 4; j++) {
                int row = wn * 32 + j * 8 + lb_row;
                ldsm_x2(Bf[j][0], Bf[j][1], sBh + sw(row, ch_b));
            }
            #pragma unroll
            for (int i = 0; i < 4; i++)
                #pragma unroll
                for (int j = 0; j < 4; j++) mma16816(acc[i][j], Af[i], Bf[j]);
        }
    }

    // Epilogue: registers -> gmem with bias
    const int g = lane >> 2, q = lane & 3;
    #pragma unroll
    for (int i = 0; i < 4; i++) {
        const int row0 = mBase + wm * 64 + i * 16 + g;
        #pragma unroll
        for (int j = 0; j < 4; j++) {
            const int col = nBase + wn * 32 + j * 8 + q * 2;
            float2 bb = *(const float2*)(bias + col);
            float2 v0 = make_float2(acc[i][j][0] + bb.x, acc[i][j][1] + bb.y);
            float2 v1 = make_float2(acc[i][j][2] + bb.x, acc[i][j][3] + bb.y);
            *(float2*)(out + (size_t)row0 * N + col)       = v0;
            *(float2*)(out + (size_t)(row0 + 8) * N + col) = v1;
        }
    }
}

// ---------------------------------------------------------------------------
// Flash-attention (fp32, causal). Epilogue writes split-bf16 for proj GEMM.
// ---------------------------------------------------------------------------
#define SMEM_ATTN ((64*65 + 64*64 + 64*65 + 64*64)*4)

__global__ void __launch_bounds__(256) attn_kernel(const float* __restrict__ qkv,
                                                   unsigned short* __restrict__ atth,
                                                   unsigned short* __restrict__ attl)
{
    extern __shared__ float smf[];
    float* Qs = smf;               // [64][65]
    float* Ks = Qs + 64*65;        // [64][64] KsT[d][k], swizzled
    float* Ps = Ks + 64*64;        // [64][65]
    float* Vs = Ps + 64*65;        // [64][64]

    const int tid = threadIdx.x;
    const int ty = tid >> 4, tx = tid & 15;
    const int ty4 = ty << 2, tx4 = tx << 2;
    const int bh = blockIdx.y;
    const int b = bh >> 4, hd = bh & 15;
    const int qt = (int)gridDim.x - 1 - (int)blockIdx.x;
    const int q0 = qt << 6;
    const size_t ld = 3 * C_;
    const float* qbase = qkv + (size_t)b * T_ * ld + hd * D_;
    const float* kbase = qbase + C_;
    const float* vbase = qbase + 2 * C_;

    #pragma unroll
    for (int it = 0; it < 4; it++) {
        int e = it*256 + tid;
        int r = e >> 4;
        int d4 = (e & 15) << 2;
        float4 v = *(const float4*)(qbase + (size_t)(q0 + r)*ld + d4);
        float* dst = Qs + r*65 + d4;
        dst[0]=v.x; dst[1]=v.y; dst[2]=v.z; dst[3]=v.w;
    }

    float m[4], l[4], o[4][4];
    #pragma unroll
    for (int i = 0; i < 4; i++) {
        m[i] = -1e30f; l[i] = 0.f;
        #pragma unroll
        for (int j = 0; j < 4; j++) o[i][j] = 0.f;
    }

    for (int kt = 0; kt <= qt; kt++) {
        const int k0 = kt << 6;
        __syncthreads();
        #pragma unroll
        for (int it = 0; it < 4; it++) {
            int e = it*256 + tid;
            int r = e >> 4;
            int mm = e & 15;
            int d4 = mm << 2;
            float4 kv = *(const float4*)(kbase + (size_t)(k0 + r)*ld + d4);
            int pos = ((((r >> 2) ^ mm) << 2) | (r & 3));
            Ks[(d4+0)*64 + pos] = kv.x;
            Ks[(d4+1)*64 + pos] = kv.y;
            Ks[(d4+2)*64 + pos] = kv.z;
            Ks[(d4+3)*64 + pos] = kv.w;
            float4 vv = *(const float4*)(vbase + (size_t)(k0 + r)*ld + d4);
            *(float4*)(Vs + r*64 + d4) = vv;
        }
        __syncthreads();

        float s[4][4];
        #pragma unroll
        for (int i = 0; i < 4; i++)
            #pragma unroll
            for (int j = 0; j < 4; j++) s[i][j] = 0.f;

        #pragma unroll 16
        for (int d = 0; d < 64; d++) {
            float q0r = Qs[(ty4+0)*65 + d];
            float q1r = Qs[(ty4+1)*65 + d];
            float q2r = Qs[(ty4+2)*65 + d];
            float q3r = Qs[(ty4+3)*65 + d];
            const float4 kv = *(const float4*)(Ks + d*64 + ((tx ^ ((d >> 2) & 15)) << 2));
            s[0][0] += q0r*kv.x; s[0][1] += q0r*kv.y; s[0][2] += q0r*kv.z; s[0][3] += q0r*kv.w;
            s[1][0] += q1r*kv.x; s[1][1] += q1r*kv.y; s[1][2] += q1r*kv.z; s[1][3] += q1r*kv.w;
            s[2][0] += q2r*kv.x; s[2][1] += q2r*kv.y; s[2][2] += q2r*kv.z; s[2][3] += q2r*kv.w;
            s[3][0] += q3r*kv.x; s[3][1] += q3r*kv.y; s[3][2] += q3r*kv.z; s[3][3] += q3r*kv.w;
        }

        const bool diag = (kt == qt);
        #pragma unroll
        for (int i = 0; i < 4; i++) {
            float rm = -1e30f;
            #pragma unroll
            for (int j = 0; j < 4; j++) {
                float sv = s[i][j] * 0.125f;
                if (diag && (tx4 + j) > (ty4 + i)) sv = -1e30f;
                s[i][j] = sv;
                rm = fmaxf(rm, sv);
            }
            rm = fmaxf(rm, __shfl_xor_sync(0xffffffffu, rm, 8));
            rm = fmaxf(rm, __shfl_xor_sync(0xffffffffu, rm, 4));
            rm = fmaxf(rm, __shfl_xor_sync(0xffffffffu, rm, 2));
            rm = fmaxf(rm, __shfl_xor_sync(0xffffffffu, rm, 1));
            float mn = fmaxf(m[i], rm);
            float corr = __expf(m[i] - mn);
            float ps = 0.f;
            #pragma unroll
            for (int j = 0; j < 4; j++) {
                float p = __expf(s[i][j] - mn);
                s[i][j] = p;
                ps += p;
            }
            ps += __shfl_xor_sync(0xffffffffu, ps, 8);
            ps += __shfl_xor_sync(0xffffffffu, ps, 4);
            ps += __shfl_xor_sync(0xffffffffu, ps, 2);
            ps += __shfl_xor_sync(0xffffffffu, ps, 1);
            l[i] = l[i]*corr + ps;
            m[i] = mn;
            #pragma unroll
            for (int j = 0; j < 4; j++) o[i][j] *= corr;
            float* pr = Ps + (ty4+i)*65 + tx4;
            pr[0] = s[i][0]; pr[1] = s[i][1]; pr[2] = s[i][2]; pr[3] = s[i][3];
        }
        __syncthreads();

        #pragma unroll 16
        for (int k = 0; k < 64; k++) {
            float p0 = Ps[(ty4+0)*65 + k];
            float p1 = Ps[(ty4+1)*65 + k];
            float p2 = Ps[(ty4+2)*65 + k];
            float p3 = Ps[(ty4+3)*65 + k];
            const float4 vv = *(const float4*)(Vs + k*64 + tx4);
            o[0][0] += p0*vv.x; o[0][1] += p0*vv.y; o[0][2] += p0*vv.z; o[0][3] += p0*vv.w;
            o[1][0] += p1*vv.x; o[1][1] += p1*vv.y; o[1][2] += p1*vv.z; o[1][3] += p1*vv.w;
            o[2][0] += p2*vv.x; o[2][1] += p2*vv.y; o[2][2] += p2*vv.z; o[2][3] += p2*vv.w;
            o[3][0] += p3*vv.x; o[3][1] += p3*vv.y; o[3][2] += p3*vv.z; o[3][3] += p3*vv.w;
        }
    }

    // Epilogue: normalize and write split-bf16 [b*T+t][hd*64+d]
    const size_t rbase = (size_t)(b*T_ + q0);
    const int col = hd * D_ + tx4;
    #pragma unroll
    for (int i = 0; i < 4; i++) {
        float inv = 1.f / l[i];
        unsigned short hh[4], ll[4];
        split2(o[i][0]*inv, hh[0], ll[0]);
        split2(o[i][1]*inv, hh[1], ll[1]);
        split2(o[i][2]*inv, hh[2], ll[2]);
        split2(o[i][3]*inv, hh[3], ll[3]);
        size_t off = (rbase + ty4 + i) * C_ + col;
        *(uint2*)(atth + off) = make_uint2((uint32_t)hh[0] | ((uint32_t)hh[1] << 16),
                                           (uint32_t)hh[2] | ((uint32_t)hh[3] << 16));
        *(uint2*)(attl + off) = make_uint2((uint32_t)ll[0] | ((uint32_t)ll[1] << 16),
                                           (uint32_t)ll[2] | ((uint32_t)ll[3] << 16));
    }
}

// ---------------------------------------------------------------------------
extern "C" void kernel_launch(void* const* d_in, const int* in_sizes, int n_in,
                              void* d_out, int out_size)
{
    const float* x      = (const float*)d_in[0];
    const float* w_qkv  = (const float*)d_in[1];
    const float* b_qkv  = (const float*)d_in[2];
    const float* w_proj = (const float*)d_in[3];
    const float* b_proj = (const float*)d_in[4];
    float* out = (float*)d_out;

    float *qkv_ptr = nullptr;
    unsigned short *xh, *xl, *wqh, *wql, *wph, *wpl, *ath, *atl;
    cudaGetSymbolAddress((void**)&qkv_ptr, g_qkv);
    cudaGetSymbolAddress((void**)&xh, g_xh);
    cudaGetSymbolAddress((void**)&xl, g_xl);
    cudaGetSymbolAddress((void**)&wqh, g_wqkvh);
    cudaGetSymbolAddress((void**)&wql, g_wqkvl);
    cudaGetSymbolAddress((void**)&wph, g_wprojh);
    cudaGetSymbolAddress((void**)&wpl, g_wprojl);
    cudaGetSymbolAddress((void**)&ath, g_atth);
    cudaGetSymbolAddress((void**)&atl, g_attl);

    cudaFuncSetAttribute(gemm_mma_kernel,
                         cudaFuncAttributeMaxDynamicSharedMemorySize, GEMM_SMEM);
    cudaFuncSetAttribute(attn_kernel,
                         cudaFuncAttributeMaxDynamicSharedMemorySize, SMEM_ATTN);

    // 0) pack inputs to split bf16
    pack_split_kernel<<<M_*C_/1024, 256>>>(x, xh, xl);
    transpose_pack_kernel<<<dim3(3*C_/32, C_/32), dim3(32, 8)>>>(w_qkv, wqh, wql, C_, 3*C_);
    transpose_pack_kernel<<<dim3(C_/32, C_/32), dim3(32, 8)>>>(w_proj, wph, wpl, C_, C_);

    // 1) qkv = x @ w_qkv + b_qkv  (mma.sync split-bf16)
    gemm_mma_kernel<<<dim3(3*C_/128, M_/128), 256, GEMM_SMEM>>>(
        xh, xl, wqh, wql, b_qkv, qkv_ptr, M_, 3*C_, C_);

    // 2) causal flash attention -> split-bf16 att
    attn_kernel<<<dim3(T_/64, B_*H_), 256, SMEM_ATTN>>>(qkv_ptr, ath, atl);

    // 3) out = att @ w_proj + b_proj  (mma.sync split-bf16)
    gemm_mma_kernel<<<dim3(C_/128, M_/128), 256, GEMM_SMEM>>>(
        ath, atl, wph, wpl, b_proj, out, M_, C_, C_);
}

// round 6
// speedup vs baseline: 3.2130x; 1.8779x over previous
#include <cuda_runtime.h>
#include <cuda_bf16.h>
#include <stdint.h>
#include <math.h>

#define B_ 4
#define T_ 2048
#define C_ 1024
#define H_ 16
#define D_ 64
#define M_ (B_*T_)   // 8192

// ---------------------------------------------------------------------------
// Scratch (allocation-free __device__ globals)
// ---------------------------------------------------------------------------
__device__ unsigned short g_qkvh[25165824];    // qkv hi bf16 [8192][3072]
__device__ unsigned short g_qkvl[25165824];    // qkv lo
__device__ unsigned short g_xh[8388608];       // x hi bf16 [8192][1024]
__device__ unsigned short g_xl[8388608];
__device__ unsigned short g_wqkvh[3145728];    // w_qkv^T hi [3072][1024]
__device__ unsigned short g_wqkvl[3145728];
__device__ unsigned short g_wprojh[1048576];   // w_proj^T hi [1024][1024]
__device__ unsigned short g_wprojl[1048576];
__device__ unsigned short g_atth[8388608];     // attention out hi [8192][1024]
__device__ unsigned short g_attl[8388608];

// ---------------------------------------------------------------------------
// Helpers (sm_103 baseline: ldmatrix, mma.sync, cp.async)
// ---------------------------------------------------------------------------
__device__ __forceinline__ uint32_t smem_u32(const void* p) {
    uint32_t a;
    asm("{ .reg .u64 t; cvta.to.shared.u64 t, %1; cvt.u32.u64 %0, t; }"
        : "=r"(a) : "l"(p));
    return a;
}

__device__ __forceinline__ void ldsm_x4(uint32_t& r0, uint32_t& r1,
                                        uint32_t& r2, uint32_t& r3, uint32_t a) {
    asm volatile("ldmatrix.sync.aligned.m8n8.x4.shared.b16 {%0,%1,%2,%3}, [%4];"
                 : "=r"(r0), "=r"(r1), "=r"(r2), "=r"(r3) : "r"(a));
}

__device__ __forceinline__ void ldsm_x2(uint32_t& r0, uint32_t& r1, uint32_t a) {
    asm volatile("ldmatrix.sync.aligned.m8n8.x2.shared.b16 {%0,%1}, [%2];"
                 : "=r"(r0), "=r"(r1) : "r"(a));
}

__device__ __forceinline__ void ldsm_x4t(uint32_t* r, uint32_t a) {
    asm volatile("ldmatrix.sync.aligned.m8n8.x4.trans.shared.b16 {%0,%1,%2,%3}, [%4];"
                 : "=r"(r[0]), "=r"(r[1]), "=r"(r[2]), "=r"(r[3]) : "r"(a));
}

__device__ __forceinline__ void mma16816(float* c, const uint32_t* A, const uint32_t* Bv) {
    asm volatile(
        "mma.sync.aligned.m16n8k16.row.col.f32.bf16.bf16.f32 "
        "{%0,%1,%2,%3}, {%4,%5,%6,%7}, {%8,%9}, {%0,%1,%2,%3};"
        : "+f"(c[0]), "+f"(c[1]), "+f"(c[2]), "+f"(c[3])
        : "r"(A[0]), "r"(A[1]), "r"(A[2]), "r"(A[3]), "r"(Bv[0]), "r"(Bv[1]));
}

__device__ __forceinline__ void cp16(uint32_t dst, const void* src) {
    asm volatile("cp.async.cg.shared.global [%0], [%1], 16;" :: "r"(dst), "l"(src));
}
#define CP_COMMIT() asm volatile("cp.async.commit_group;" ::: "memory")

// pack two fp32 -> bf16x2 {lo=p0, hi=p1}
__device__ __forceinline__ uint32_t pack_bf16(float p0, float p1) {
    uint32_t r;
    asm("cvt.rn.bf16x2.f32 %0, %1, %2;" : "=r"(r) : "f"(p1), "f"(p0));
    return r;
}

// split pair into hi bf16x2 + residual bf16x2
__device__ __forceinline__ void mk2(float p0, float p1, uint32_t& hi, uint32_t& lo) {
    uint32_t h = pack_bf16(p0, p1);
    float r0 = p0 - __uint_as_float(h << 16);
    float r1 = p1 - __uint_as_float(h & 0xffff0000u);
    hi = h;
    lo = pack_bf16(r0, r1);
}

__device__ __forceinline__ void split2(float x, unsigned short& hh, unsigned short& ll) {
    __nv_bfloat16 hb = __float2bfloat16(x);
    hh = reinterpret_cast<unsigned short&>(hb);
    float r = x - __bfloat162float(hb);
    __nv_bfloat16 lb = __float2bfloat16(r);
    ll = reinterpret_cast<unsigned short&>(lb);
}

// ---------------------------------------------------------------------------
// Prep kernels
// ---------------------------------------------------------------------------
__global__ void __launch_bounds__(256) pack_split_kernel(
    const float* __restrict__ src, unsigned short* __restrict__ hi,
    unsigned short* __restrict__ lo)
{
    int i = blockIdx.x * 256 + threadIdx.x;
    float4 v = ((const float4*)src)[i];
    unsigned short h[4], l[4];
    split2(v.x, h[0], l[0]); split2(v.y, h[1], l[1]);
    split2(v.z, h[2], l[2]); split2(v.w, h[3], l[3]);
    ((uint2*)hi)[i] = make_uint2((uint32_t)h[0] | ((uint32_t)h[1] << 16),
                                 (uint32_t)h[2] | ((uint32_t)h[3] << 16));
    ((uint2*)lo)[i] = make_uint2((uint32_t)l[0] | ((uint32_t)l[1] << 16),
                                 (uint32_t)l[2] | ((uint32_t)l[3] << 16));
}

__global__ void __launch_bounds__(256) transpose_pack_kernel(
    const float* __restrict__ w, unsigned short* __restrict__ th,
    unsigned short* __restrict__ tl, int K, int N)
{
    __shared__ float tile[32][33];
    const int k0 = blockIdx.y * 32, n0 = blockIdx.x * 32;
    const int tx = threadIdx.x, ty = threadIdx.y;   // 32 x 8
    #pragma unroll
    for (int i = 0; i < 32; i += 8)
        tile[ty + i][tx] = w[(size_t)(k0 + ty + i) * N + n0 + tx];
    __syncthreads();
    #pragma unroll
    for (int i = 0; i < 32; i += 8) {
        int n = n0 + ty + i;
        int k = k0 + tx;
        float v = tile[tx][ty + i];
        unsigned short hh, ll;
        split2(v, hh, ll);
        th[(size_t)n * K + k] = hh;
        tl[(size_t)n * K + k] = ll;
    }
}

// ---------------------------------------------------------------------------
// Split-bf16 mma.sync GEMM: out = A @ B^T + bias.
// Output either fp32 (outf) or split-bf16 (outh/outl).
// ---------------------------------------------------------------------------
#define GEMM_SMEM 65536

__global__ void __launch_bounds__(256) gemm_mma_kernel(
    const unsigned short* __restrict__ ah, const unsigned short* __restrict__ al,
    const unsigned short* __restrict__ bh, const unsigned short* __restrict__ bl,
    const float* __restrict__ bias, float* __restrict__ outf,
    unsigned short* __restrict__ outh, unsigned short* __restrict__ outl,
    int M, int N, int K)
{
    extern __shared__ char smc[];
    const uint32_t sbase = smem_u32(smc);
    const int tid  = threadIdx.x;
    const int wid  = tid >> 5, lane = tid & 31;
    const int wm   = wid >> 2, wn = wid & 3;
    const int mBase = blockIdx.y * 128;
    const int nBase = blockIdx.x * 128;
    const int nk = K >> 5;

    const int r0c = tid >> 2;
    const int c0c = tid & 3;
    auto sw = [](int r, int c) { return r * 64 + ((c ^ ((r >> 1) & 3)) << 4); };

    auto issue = [&](int ks, int stage) {
        const int kb = ks << 5;
        const unsigned short* gs[4] = { ah, al, bh, bl };
        #pragma unroll
        for (int part = 0; part < 4; part++) {
            const unsigned short* g = gs[part] +
                (size_t)((part < 2) ? mBase : nBase) * K + kb;
            uint32_t pb = sbase + stage * 32768 + part * 8192;
            cp16(pb + sw(r0c,      c0c), g + (size_t)r0c        * K + c0c * 8);
            cp16(pb + sw(r0c + 64, c0c), g + (size_t)(r0c + 64) * K + c0c * 8);
        }
        CP_COMMIT();
    };

    float acc[4][4][4];
    #pragma unroll
    for (int i = 0; i < 4; i++)
        #pragma unroll
        for (int j = 0; j < 4; j++)
            #pragma unroll
            for (int r = 0; r < 4; r++) acc[i][j][r] = 0.f;

    const int la_row = lane & 15;
    const int la_kh  = lane >> 4;
    const int lb_row = lane & 7;
    const int lb_kh  = (lane >> 3) & 1;

    issue(0, 0);

    for (int ks = 0; ks < nk; ks++) {
        const int cur = ks & 1;
        asm volatile("cp.async.wait_group 0;" ::: "memory");
        __syncthreads();
        if (ks + 1 < nk) issue(ks + 1, cur ^ 1);

        const uint32_t sAh = sbase + cur * 32768;
        const uint32_t sAl = sAh + 8192;
        const uint32_t sBh = sAh + 16384;
        const uint32_t sBl = sAh + 24576;

        #pragma unroll
        for (int kk = 0; kk < 2; kk++) {
            uint32_t Af[4][4], Bf[4][2];
            const int ch_a = kk * 2 + la_kh;
            const int ch_b = kk * 2 + lb_kh;

            #pragma unroll
            for (int i = 0; i < 4; i++) {
                int row = wm * 64 + i * 16 + la_row;
                ldsm_x4(Af[i][0], Af[i][1], Af[i][2], Af[i][3], sAh + sw(row, ch_a));
            }
            #pragma unroll
            for (int j = 0; j < 4; j++) {
                int row = wn * 32 + j * 8 + lb_row;
                ldsm_x2(Bf[j][0], Bf[j][1], sBh + sw(row, ch_b));
            }
            #pragma unroll
            for (int i = 0; i < 4; i++)
                #pragma unroll
                for (int j = 0; j < 4; j++) mma16816(acc[i][j], Af[i], Bf[j]);

            #pragma unroll
            for (int j = 0; j < 4; j++) {
                int row = wn * 32 + j * 8 + lb_row;
                ldsm_x2(Bf[j][0], Bf[j][1], sBl + sw(row, ch_b));
            }
            #pragma unroll
            for (int i = 0; i < 4; i++)
                #pragma unroll
                for (int j = 0; j < 4; j++) mma16816(acc[i][j], Af[i], Bf[j]);

            #pragma unroll
            for (int i = 0; i < 4; i++) {
                int row = wm * 64 + i * 16 + la_row;
                ldsm_x4(Af[i][0], Af[i][1], Af[i][2], Af[i][3], sAl + sw(row, ch_a));
            }
            #pragma unroll
            for (int j = 0; j < 4; j++) {
                int row = wn * 32 + j * 8 + lb_row;
                ldsm_x2(Bf[j][0], Bf[j][1], sBh + sw(row, ch_b));
            }
            #pragma unroll
            for (int i = 0; i < 4; i++)
                #pragma unroll
                for (int j = 0; j < 4; j++) mma16816(acc[i][j], Af[i], Bf[j]);
        }
    }

    // Epilogue
    const int g = lane >> 2, q = lane & 3;
    #pragma unroll
    for (int i = 0; i < 4; i++) {
        const int row0 = mBase + wm * 64 + i * 16 + g;
        #pragma unroll
        for (int j = 0; j < 4; j++) {
            const int col = nBase + wn * 32 + j * 8 + q * 2;
            float2 bb = *(const float2*)(bias + col);
            float v0x = acc[i][j][0] + bb.x, v0y = acc[i][j][1] + bb.y;
            float v1x = acc[i][j][2] + bb.x, v1y = acc[i][j][3] + bb.y;
            if (outh) {
                uint32_t h0, l0, h1, l1;
                mk2(v0x, v0y, h0, l0);
                mk2(v1x, v1y, h1, l1);
                *(uint32_t*)(outh + (size_t)row0 * N + col)       = h0;
                *(uint32_t*)(outl + (size_t)row0 * N + col)       = l0;
                *(uint32_t*)(outh + (size_t)(row0 + 8) * N + col) = h1;
                *(uint32_t*)(outl + (size_t)(row0 + 8) * N + col) = l1;
            } else {
                *(float2*)(outf + (size_t)row0 * N + col)       = make_float2(v0x, v0y);
                *(float2*)(outf + (size_t)(row0 + 8) * N + col) = make_float2(v1x, v1y);
            }
        }
    }
}

// ---------------------------------------------------------------------------
// Tensor-core flash attention (causal, split-bf16).
// Block = 128 q rows of one (b,h), 8 warps (m16 each), 256 threads.
// K tiles of 64; K/V double-buffered via cp.async; Q resident in smem.
// Smem: Qh 16K | Ql 16K | 2 stages x (Kh|Kl|Vh|Vl 8K each) = 96KB.
// ---------------------------------------------------------------------------
#define ATTN_SMEM 98304

__global__ void __launch_bounds__(256, 1) attn_mma_kernel(
    const unsigned short* __restrict__ qkvh,
    const unsigned short* __restrict__ qkvl,
    unsigned short* __restrict__ atth,
    unsigned short* __restrict__ attl)
{
    extern __shared__ char smc[];
    const uint32_t sb = smem_u32(smc);
    const int tid = threadIdx.x, lane = tid & 31, w = tid >> 5;
    const int bh = blockIdx.y, b = bh >> 4, hd = bh & 15;
    const int qb = (int)gridDim.x - 1 - (int)blockIdx.x;   // big blocks first
    const int q0 = qb * 128;
    const int nkt = 2 * qb + 2;

    const size_t base = (size_t)b * T_ * 3072 + hd * 64;
    const unsigned short* qh = qkvh + base;
    const unsigned short* qlp = qkvl + base;
    const unsigned short* kh = qh + 1024;
    const unsigned short* kl = qlp + 1024;
    const unsigned short* vh = qh + 2048;
    const unsigned short* vl = qlp + 2048;

    const uint32_t sQh = sb, sQl = sb + 16384;
    auto stage0 = [&](int s) { return sb + 32768 + s * 32768; };
    auto off = [](int r, int c) { return r * 128 + ((c ^ (r & 7)) << 4); };

    // prologue: Q (128 rows) + tile 0 (K/V 64 rows)
    #pragma unroll
    for (int i = 0; i < 4; i++) {
        int idx = i * 256 + tid;
        int r = idx >> 3, c = idx & 7;
        const size_t g = (size_t)(q0 + r) * 3072 + c * 8;
        cp16(sQh + off(r, c), qh + g);
        cp16(sQl + off(r, c), qlp + g);
    }
    {
        uint32_t s0 = stage0(0);
        #pragma unroll
        for (int i = 0; i < 2; i++) {
            int idx = i * 256 + tid;
            int r = idx >> 3, c = idx & 7;
            const size_t g = (size_t)r * 3072 + c * 8;
            cp16(s0 +         off(r, c), kh + g);
            cp16(s0 + 8192 +  off(r, c), kl + g);
            cp16(s0 + 16384 + off(r, c), vh + g);
            cp16(s0 + 24576 + off(r, c), vl + g);
        }
    }
    CP_COMMIT();

    float O[8][4], s[8][4];
    #pragma unroll
    for (int j = 0; j < 8; j++) { O[j][0] = O[j][1] = O[j][2] = O[j][3] = 0.f; }
    float m_lo = -1e30f, m_hi = -1e30f, l_lo = 0.f, l_hi = 0.f;

    const int la_row = lane & 15, la_kh = lane >> 4;
    const int kb_row = ((lane >> 4) << 3) + (lane & 7);   // K B-frag rows
    const int kb_ch  = (lane >> 3) & 1;
    const int vb_row = (((lane >> 3) & 1) << 3) + (lane & 7);  // V trans rows
    const int vb_ch  = lane >> 4;
    const int rowq_lo = q0 + w * 16 + (lane >> 2);

    for (int kt = 0; kt < nkt; kt++) {
        __syncthreads();   // all warps done reading stage being overwritten
        if (kt + 1 < nkt) {
            uint32_t sn = stage0((kt + 1) & 1);
            const size_t kb = (size_t)(kt + 1) * 64;
            #pragma unroll
            for (int i = 0; i < 2; i++) {
                int idx = i * 256 + tid;
                int r = idx >> 3, c = idx & 7;
                const size_t g = (kb + r) * 3072 + c * 8;
                cp16(sn +         off(r, c), kh + g);
                cp16(sn + 8192 +  off(r, c), kl + g);
                cp16(sn + 16384 + off(r, c), vh + g);
                cp16(sn + 24576 + off(r, c), vl + g);
            }
            CP_COMMIT();
            asm volatile("cp.async.wait_group 1;" ::: "memory");
        } else {
            asm volatile("cp.async.wait_group 0;" ::: "memory");
        }
        __syncthreads();   // make stage visible to all warps

        const int k0 = kt * 64;
        const bool active = (k0 <= q0 + w * 16 + 15);
        if (active) {
            const uint32_t cK  = stage0(kt & 1);
            const uint32_t cKl = cK + 8192;
            const uint32_t cV  = cK + 16384;
            const uint32_t cVl = cK + 24576;

            // ---- S = Q K^T (split: QhKh + QlKh + QhKl) ----
            #pragma unroll
            for (int j = 0; j < 8; j++) { s[j][0] = s[j][1] = s[j][2] = s[j][3] = 0.f; }
            #pragma unroll
            for (int kk = 0; kk < 4; kk++) {
                uint32_t aqh[4], aql[4];
                ldsm_x4(aqh[0], aqh[1], aqh[2], aqh[3],
                        sQh + off(w * 16 + la_row, 2 * kk + la_kh));
                ldsm_x4(aql[0], aql[1], aql[2], aql[3],
                        sQl + off(w * 16 + la_row, 2 * kk + la_kh));
                #pragma unroll
                for (int j2 = 0; j2 < 4; j2++) {
                    uint32_t bk[4];
                    ldsm_x4(bk[0], bk[1], bk[2], bk[3],
                            cK + off(16 * j2 + kb_row, 2 * kk + kb_ch));
                    mma16816(s[2 * j2],     aqh, bk);
                    mma16816(s[2 * j2 + 1], aqh, bk + 2);
                    mma16816(s[2 * j2],     aql, bk);
                    mma16816(s[2 * j2 + 1], aql, bk + 2);
                    ldsm_x4(bk[0], bk[1], bk[2], bk[3],
                            cKl + off(16 * j2 + kb_row, 2 * kk + kb_ch));
                    mma16816(s[2 * j2],     aqh, bk);
                    mma16816(s[2 * j2 + 1], aqh, bk + 2);
                }
            }

            // ---- online softmax ----
            const bool masked = (k0 + 63 > q0 + w * 16);
            float rm_lo = -1e30f, rm_hi = -1e30f;
            #pragma unroll
            for (int j = 0; j < 8; j++) {
                int colb = k0 + 8 * j + 2 * (lane & 3);
                #pragma unroll
                for (int e = 0; e < 2; e++) {
                    float v = s[j][e] * 0.125f;
                    if (masked && (colb + e) > rowq_lo) v = -1e30f;
                    s[j][e] = v; rm_lo = fmaxf(rm_lo, v);
                    float v2 = s[j][2 + e] * 0.125f;
                    if (masked && (colb + e) > rowq_lo + 8) v2 = -1e30f;
                    s[j][2 + e] = v2; rm_hi = fmaxf(rm_hi, v2);
                }
            }
            rm_lo = fmaxf(rm_lo, __shfl_xor_sync(0xffffffffu, rm_lo, 1));
            rm_lo = fmaxf(rm_lo, __shfl_xor_sync(0xffffffffu, rm_lo, 2));
            rm_hi = fmaxf(rm_hi, __shfl_xor_sync(0xffffffffu, rm_hi, 1));
            rm_hi = fmaxf(rm_hi, __shfl_xor_sync(0xffffffffu, rm_hi, 2));
            float mn_lo = fmaxf(m_lo, rm_lo), mn_hi = fmaxf(m_hi, rm_hi);
            float corr_lo = __expf(m_lo - mn_lo), corr_hi = __expf(m_hi - mn_hi);
            m_lo = mn_lo; m_hi = mn_hi;
            float ps_lo = 0.f, ps_hi = 0.f;
            #pragma unroll
            for (int j = 0; j < 8; j++) {
                s[j][0] = __expf(s[j][0] - mn_lo);
                s[j][1] = __expf(s[j][1] - mn_lo);
                s[j][2] = __expf(s[j][2] - mn_hi);
                s[j][3] = __expf(s[j][3] - mn_hi);
                ps_lo += s[j][0] + s[j][1];
                ps_hi += s[j][2] + s[j][3];
            }
            ps_lo += __shfl_xor_sync(0xffffffffu, ps_lo, 1);
            ps_lo += __shfl_xor_sync(0xffffffffu, ps_lo, 2);
            ps_hi += __shfl_xor_sync(0xffffffffu, ps_hi, 1);
            ps_hi += __shfl_xor_sync(0xffffffffu, ps_hi, 2);
            l_lo = l_lo * corr_lo + ps_lo;
            l_hi = l_hi * corr_hi + ps_hi;
            #pragma unroll
            for (int j = 0; j < 8; j++) {
                O[j][0] *= corr_lo; O[j][1] *= corr_lo;
                O[j][2] *= corr_hi; O[j][3] *= corr_hi;
            }

            // ---- O += P V (split: PhVh + PlVh + PhVl) ----
            #pragma unroll
            for (int t = 0; t < 4; t++) {
                uint32_t ph[4], pl[4];
                mk2(s[2 * t][0],     s[2 * t][1],     ph[0], pl[0]);
                mk2(s[2 * t][2],     s[2 * t][3],     ph[1], pl[1]);
                mk2(s[2 * t + 1][0], s[2 * t + 1][1], ph[2], pl[2]);
                mk2(s[2 * t + 1][2], s[2 * t + 1][3], ph[3], pl[3]);
                #pragma unroll
                for (int j2 = 0; j2 < 4; j2++) {
                    uint32_t bv[4];
                    ldsm_x4t(bv, cV + off(16 * t + vb_row, 2 * j2 + vb_ch));
                    mma16816(O[2 * j2],     ph, bv);
                    mma16816(O[2 * j2 + 1], ph, bv + 2);
                    mma16816(O[2 * j2],     pl, bv);
                    mma16816(O[2 * j2 + 1], pl, bv + 2);
                    ldsm_x4t(bv, cVl + off(16 * t + vb_row, 2 * j2 + vb_ch));
                    mma16816(O[2 * j2],     ph, bv);
                    mma16816(O[2 * j2 + 1], ph, bv + 2);
                }
            }
        }
    }

    // ---- epilogue: normalize, split-bf16, write ----
    const float inv_lo = 1.f / l_lo, inv_hi = 1.f / l_hi;
    const size_t row_lo = (size_t)(b * T_) + q0 + w * 16 + (lane >> 2);
    const int colb = hd * 64 + 2 * (lane & 3);
    #pragma unroll
    for (int j = 0; j < 8; j++) {
        const int col = colb + 8 * j;
        uint32_t h0, l0, h1, l1;
        mk2(O[j][0] * inv_lo, O[j][1] * inv_lo, h0, l0);
        mk2(O[j][2] * inv_hi, O[j][3] * inv_hi, h1, l1);
        *(uint32_t*)(atth + row_lo * C_ + col)       = h0;
        *(uint32_t*)(attl + row_lo * C_ + col)       = l0;
        *(uint32_t*)(atth + (row_lo + 8) * C_ + col) = h1;
        *(uint32_t*)(attl + (row_lo + 8) * C_ + col) = l1;
    }
}

// ---------------------------------------------------------------------------
extern "C" void kernel_launch(void* const* d_in, const int* in_sizes, int n_in,
                              void* d_out, int out_size)
{
    const float* x      = (const float*)d_in[0];
    const float* w_qkv  = (const float*)d_in[1];
    const float* b_qkv  = (const float*)d_in[2];
    const float* w_proj = (const float*)d_in[3];
    const float* b_proj = (const float*)d_in[4];
    float* out = (float*)d_out;

    unsigned short *qvh, *qvl, *xh, *xl, *wqh, *wql, *wph, *wpl, *ath, *atl;
    cudaGetSymbolAddress((void**)&qvh, g_qkvh);
    cudaGetSymbolAddress((void**)&qvl, g_qkvl);
    cudaGetSymbolAddress((void**)&xh, g_xh);
    cudaGetSymbolAddress((void**)&xl, g_xl);
    cudaGetSymbolAddress((void**)&wqh, g_wqkvh);
    cudaGetSymbolAddress((void**)&wql, g_wqkvl);
    cudaGetSymbolAddress((void**)&wph, g_wprojh);
    cudaGetSymbolAddress((void**)&wpl, g_wprojl);
    cudaGetSymbolAddress((void**)&ath, g_atth);
    cudaGetSymbolAddress((void**)&atl, g_attl);

    cudaFuncSetAttribute(gemm_mma_kernel,
                         cudaFuncAttributeMaxDynamicSharedMemorySize, GEMM_SMEM);
    cudaFuncSetAttribute(attn_mma_kernel,
                         cudaFuncAttributeMaxDynamicSharedMemorySize, ATTN_SMEM);

    // 0) pack inputs to split bf16
    pack_split_kernel<<<M_*C_/1024, 256>>>(x, xh, xl);
    transpose_pack_kernel<<<dim3(3*C_/32, C_/32), dim3(32, 8)>>>(w_qkv, wqh, wql, C_, 3*C_);
    transpose_pack_kernel<<<dim3(C_/32, C_/32), dim3(32, 8)>>>(w_proj, wph, wpl, C_, C_);

    // 1) qkv = x @ w_qkv + b_qkv  -> split-bf16 qkv
    gemm_mma_kernel<<<dim3(3*C_/128, M_/128), 256, GEMM_SMEM>>>(
        xh, xl, wqh, wql, b_qkv, nullptr, qvh, qvl, M_, 3*C_, C_);

    // 2) tensor-core causal flash attention -> split-bf16 att
    attn_mma_kernel<<<dim3(T_/128, B_*H_), 256, ATTN_SMEM>>>(qvh, qvl, ath, atl);

    // 3) out = att @ w_proj + b_proj  -> fp32
    gemm_mma_kernel<<<dim3(C_/128, M_/128), 256, GEMM_SMEM>>>(
        ath, atl, wph, wpl, b_proj, out, nullptr, nullptr, M_, C_, C_);
}